// round 9
// baseline (speedup 1.0000x reference)
#include <cuda_runtime.h>
#include <cuda_bf16.h>

// Problem constants (fixed by the reference)
#define CSEG 4096
#define ED   16
#define PIX  (1024*1024)
#define NEDGE 16384
#define DELTA_VAR  0.5f
#define DELTA_DIST 1.5f

// Scratch (device globals — no runtime allocation allowed)
__device__ __align__(128) float g_sorted[(size_t)PIX * ED]; // 64 MB seg-sorted rows
__device__ __align__(128) float g_means[CSEG * ED];         // 256 KB
__device__ int   g_cnt[CSEG];
__device__ int   g_off[CSEG + 1];
__device__ int   g_cur[CSEG];
__device__ float g_invn[CSEG];
__device__ float g_acc[2];   // [0]=inter sum, [1]=intra sum

// ---------------------------------------------------------------------------
__device__ __forceinline__ float warp_reduce(float v) {
    v += __shfl_down_sync(0xFFFFFFFFu, v, 16);
    v += __shfl_down_sync(0xFFFFFFFFu, v, 8);
    v += __shfl_down_sync(0xFFFFFFFFu, v, 4);
    v += __shfl_down_sync(0xFFFFFFFFu, v, 2);
    v += __shfl_down_sync(0xFFFFFFFFu, v, 1);
    return v;
}

__device__ __forceinline__ float block_reduce(float v) {
    __shared__ float s[32];
    int lane = threadIdx.x & 31;
    int wid  = threadIdx.x >> 5;
    v = warp_reduce(v);
    if (lane == 0) s[wid] = v;
    __syncthreads();
    int nw = (blockDim.x + 31) >> 5;
    v = (threadIdx.x < nw) ? s[threadIdx.x] : 0.0f;
    if (wid == 0) v = warp_reduce(v);
    return v;
}

// ---------------------------------------------------------------------------
// kz: zero accumulators (graph replays re-run every launch)
__global__ void kz_zero() {
    int i = blockIdx.x * blockDim.x + threadIdx.x;
    if (i < CSEG) g_cnt[i] = 0;
    if (i < 2)    g_acc[i] = 0.0f;
}

// kh: histogram of segment labels. int4 loads, 4 labels per thread.
__global__ void __launch_bounds__(256) kh_hist(const int4* __restrict__ seg4) {
    int i = blockIdx.x * blockDim.x + threadIdx.x;   // over PIX/4
    int4 s = seg4[i];
    atomicAdd(&g_cnt[s.x], 1);
    atomicAdd(&g_cnt[s.y], 1);
    atomicAdd(&g_cnt[s.z], 1);
    atomicAdd(&g_cnt[s.w], 1);
}

// ks: exclusive prefix scan of counts → offsets; init cursors; 1/n. One block.
__global__ void __launch_bounds__(1024) ks_scan() {
    __shared__ int s[1024];
    int t = threadIdx.x;
    int c0 = g_cnt[4 * t + 0], c1 = g_cnt[4 * t + 1];
    int c2 = g_cnt[4 * t + 2], c3 = g_cnt[4 * t + 3];
    int tot = c0 + c1 + c2 + c3;
    s[t] = tot;
    __syncthreads();
    // inclusive Hillis-Steele scan over per-thread totals
    for (int d = 1; d < 1024; d <<= 1) {
        int v = (t >= d) ? s[t - d] : 0;
        __syncthreads();
        s[t] += v;
        __syncthreads();
    }
    int excl = s[t] - tot;
    int o0 = excl, o1 = excl + c0, o2 = o1 + c1, o3 = o2 + c2;
    g_off[4 * t + 0] = o0;  g_cur[4 * t + 0] = o0;
    g_off[4 * t + 1] = o1;  g_cur[4 * t + 1] = o1;
    g_off[4 * t + 2] = o2;  g_cur[4 * t + 2] = o2;
    g_off[4 * t + 3] = o3;  g_cur[4 * t + 3] = o3;
    if (t == 1023) g_off[CSEG] = s[1023];
    g_invn[4 * t + 0] = 1.0f / fmaxf((float)c0, 1.0f);
    g_invn[4 * t + 1] = 1.0f / fmaxf((float)c1, 1.0f);
    g_invn[4 * t + 2] = 1.0f / fmaxf((float)c2, 1.0f);
    g_invn[4 * t + 3] = 1.0f / fmaxf((float)c3, 1.0f);
}

// kt: scatter pass. Coalesced read of 16 channel planes, one atomic-return to
// claim a slot, 64 B contiguous row write into seg-sorted order (full sectors).
__global__ void __launch_bounds__(256) kt_scatter(const float* __restrict__ emb,
                                                  const int*   __restrict__ seg) {
    int p = blockIdx.x * blockDim.x + threadIdx.x;
    int c = seg[p];
    int pos = atomicAdd(&g_cur[c], 1);
    float v[ED];
#pragma unroll
    for (int e = 0; e < ED; e++) v[e] = emb[(size_t)e * PIX + p];
    float4* dst = (float4*)&g_sorted[(size_t)pos * ED];
    dst[0] = make_float4(v[0],  v[1],  v[2],  v[3]);
    dst[1] = make_float4(v[4],  v[5],  v[6],  v[7]);
    dst[2] = make_float4(v[8],  v[9],  v[10], v[11]);
    dst[3] = make_float4(v[12], v[13], v[14], v[15]);
}

// k4: one block per segment. Pass 1: atomic-free register/shfl reduction of
// the segment's rows → mean (written for the inter kernel). Pass 2: re-walk
// the same rows (L1/L2-hot, ~16 KB) for the intra hinge. One atomic per block.
__global__ void __launch_bounds__(128) k4_seg() {
    int c   = blockIdx.x;
    int beg = g_off[c], end = g_off[c + 1];
    int lane = threadIdx.x & 31, wid = threadIdx.x >> 5;

    float acc[ED];
#pragma unroll
    for (int e = 0; e < ED; e++) acc[e] = 0.0f;

    for (int i = beg + threadIdx.x; i < end; i += 128) {
        const float4* r = (const float4*)&g_sorted[(size_t)i * ED];
        float4 r0 = r[0], r1 = r[1], r2 = r[2], r3 = r[3];
        acc[0]  += r0.x; acc[1]  += r0.y; acc[2]  += r0.z; acc[3]  += r0.w;
        acc[4]  += r1.x; acc[5]  += r1.y; acc[6]  += r1.z; acc[7]  += r1.w;
        acc[8]  += r2.x; acc[9]  += r2.y; acc[10] += r2.z; acc[11] += r2.w;
        acc[12] += r3.x; acc[13] += r3.y; acc[14] += r3.z; acc[15] += r3.w;
    }

    __shared__ float sm[4][ED];
    __shared__ float smean[ED];
#pragma unroll
    for (int e = 0; e < ED; e++) acc[e] = warp_reduce(acc[e]);
    if (lane == 0) {
#pragma unroll
        for (int e = 0; e < ED; e++) sm[wid][e] = acc[e];
    }
    __syncthreads();
    if (threadIdx.x < ED) {
        float s = sm[0][threadIdx.x] + sm[1][threadIdx.x]
                + sm[2][threadIdx.x] + sm[3][threadIdx.x];
        float m = s * g_invn[c];
        smean[threadIdx.x] = m;
        g_means[c * ED + threadIdx.x] = m;
    }
    __syncthreads();

    float4 m0 = *(const float4*)&smean[0];
    float4 m1 = *(const float4*)&smean[4];
    float4 m2 = *(const float4*)&smean[8];
    float4 m3 = *(const float4*)&smean[12];

    float h = 0.0f;
    for (int i = beg + threadIdx.x; i < end; i += 128) {
        const float4* r = (const float4*)&g_sorted[(size_t)i * ED];
        float4 r0 = r[0], r1 = r[1], r2 = r[2], r3 = r[3];
        float dot = m0.x * r0.x + m0.y * r0.y + m0.z * r0.z + m0.w * r0.w
                  + m1.x * r1.x + m1.y * r1.y + m1.z * r1.z + m1.w * r1.w
                  + m2.x * r2.x + m2.y * r2.y + m2.z * r2.z + m2.w * r2.w
                  + m3.x * r3.x + m3.y * r3.y + m3.z * r3.z + m3.w * r3.w;
        // (1 - dot) - DELTA_VAR = 0.5 - dot
        h += fmaxf(0.5f - dot, 0.0f);
    }
    h = block_reduce(h);
    if (threadIdx.x == 0) atomicAdd(&g_acc[1], h * g_invn[c]);
}

// k_inter: RAG-edge hinge over superpixel means.
__global__ void __launch_bounds__(256) k_inter(const int*   __restrict__ edges,
                                               const float* __restrict__ w) {
    int i = blockIdx.x * blockDim.x + threadIdx.x;
    int u = edges[i];
    int v = edges[NEDGE + i];
    const float4* mu = (const float4*)&g_means[u * ED];
    const float4* mv = (const float4*)&g_means[v * ED];
    float dot = 0.0f;
#pragma unroll
    for (int j = 0; j < 4; j++) {
        float4 a = mu[j], b = mv[j];
        dot += a.x * b.x + a.y * b.y + a.z * b.z + a.w * b.w;
    }
    float d_inter = 1.0f - dot;
    float t = fmaxf(DELTA_DIST - d_inter * w[i], 0.0f);
    t = block_reduce(t);
    if (threadIdx.x == 0) atomicAdd(&g_acc[0], t);
}

// k_final: ALPHA * inter/NE + BETA * intra/C
__global__ void k_final(float* __restrict__ out) {
    out[0] = g_acc[0] / (float)NEDGE + g_acc[1] / (float)CSEG;
}

// ---------------------------------------------------------------------------
extern "C" void kernel_launch(void* const* d_in, const int* in_sizes, int n_in,
                              void* d_out, int out_size) {
    const float* emb   = (const float*)d_in[0];   // (1,16,1024,1024) f32
    const float* w     = (const float*)d_in[1];   // (NE,) f32
    const int*   seg   = (const int*)  d_in[2];   // (1,1,1024,1024) i32
    const int*   edges = (const int*)  d_in[3];   // (2,NE) i32
    float*       out   = (float*)d_out;

    kz_zero   <<<(CSEG + 255) / 256, 256>>>();
    kh_hist   <<<(PIX / 4) / 256, 256>>>((const int4*)seg);
    ks_scan   <<<1, 1024>>>();
    kt_scatter<<<PIX / 256, 256>>>(emb, seg);
    k4_seg    <<<CSEG, 128>>>();
    k_inter   <<<NEDGE / 256, 256>>>(edges, w);
    k_final   <<<1, 1>>>(out);
}

// round 10
// speedup vs baseline: 1.4044x; 1.4044x over previous
#include <cuda_runtime.h>
#include <cuda_bf16.h>

// Problem constants (fixed by the reference)
#define CSEG 4096
#define ED   16
#define PIX  (1024*1024)
#define NEDGE 16384
#define DELTA_VAR  0.5f
#define DELTA_DIST 1.5f

#define NBLK_INTRA (PIX / 256)     // 4096
#define NBLK_INTER (NEDGE / 256)   // 64

// Scratch (device globals — no runtime allocation allowed)
__device__ __align__(128) float g_sums[CSEG * ED];   // 256 KB segment sums
__device__ float g_counts[CSEG];
__device__ float g_acc[2];   // [0]=inter sum, [1]=intra sum

// ---------------------------------------------------------------------------
// Vector reduction to global memory (sm_90+): one L2 atomic op for 4 floats.
__device__ __forceinline__ void red_add_v4(float* addr, float a, float b, float c, float d) {
    asm volatile("red.global.add.v4.f32 [%0], {%1, %2, %3, %4};"
                 :: "l"(addr), "f"(a), "f"(b), "f"(c), "f"(d) : "memory");
}

__device__ __forceinline__ float warp_reduce(float v) {
    v += __shfl_down_sync(0xFFFFFFFFu, v, 16);
    v += __shfl_down_sync(0xFFFFFFFFu, v, 8);
    v += __shfl_down_sync(0xFFFFFFFFu, v, 4);
    v += __shfl_down_sync(0xFFFFFFFFu, v, 2);
    v += __shfl_down_sync(0xFFFFFFFFu, v, 1);
    return v;
}

// Block reduction (256 threads): full sum valid on thread 0.
__device__ __forceinline__ float block_reduce(float v) {
    __shared__ float s[8];
    int lane = threadIdx.x & 31;
    int wid  = threadIdx.x >> 5;
    v = warp_reduce(v);
    if (lane == 0) s[wid] = v;
    __syncthreads();
    if (wid == 0) {
        v = (lane < 8) ? s[lane] : 0.0f;
        v += __shfl_down_sync(0xFFFFFFFFu, v, 4);
        v += __shfl_down_sync(0xFFFFFFFFu, v, 2);
        v += __shfl_down_sync(0xFFFFFFFFu, v, 1);
    }
    return v;
}

// ---------------------------------------------------------------------------
// kz: zero accumulators (graph replays re-run every launch)
__global__ void kz_zero() {
    int i = blockIdx.x * blockDim.x + threadIdx.x;
    if (i < CSEG * ED) g_sums[i] = 0.0f;
    if (i < CSEG)      g_counts[i] = 0.0f;
    if (i < 2)         g_acc[i] = 0.0f;
}

// k_segsum: segment sums + counts. One thread per pixel; 16 coalesced strided
// channel loads, then 4 vector reds + 1 scalar red (op-minimal: 5 L2 ops/px).
__global__ void __launch_bounds__(256) k_segsum(const float* __restrict__ emb,
                                                const int*   __restrict__ seg) {
    int p = blockIdx.x * blockDim.x + threadIdx.x;
    int c = seg[p];
    float v[ED];
#pragma unroll
    for (int e = 0; e < ED; e++) v[e] = emb[(size_t)e * PIX + p];
    float* base = &g_sums[c * ED];
    red_add_v4(base +  0, v[0],  v[1],  v[2],  v[3]);
    red_add_v4(base +  4, v[4],  v[5],  v[6],  v[7]);
    red_add_v4(base +  8, v[8],  v[9],  v[10], v[11]);
    red_add_v4(base + 12, v[12], v[13], v[14], v[15]);
    atomicAdd(&g_counts[c], 1.0f);
}

// k_fused: intra hinge over all pixels (blocks [0, NBLK_INTRA)) and inter
// hinge over RAG edges (blocks [NBLK_INTRA, NBLK_INTRA+NBLK_INTER)).
// Means are never materialized: dot(mean, x) = dot(sum, x) * invn.
__global__ void __launch_bounds__(256) k_fused(const float* __restrict__ emb,
                                               const int*   __restrict__ seg,
                                               const int*   __restrict__ edges,
                                               const float* __restrict__ w) {
    if (blockIdx.x < NBLK_INTRA) {
        // ---- intra term ----
        int p = blockIdx.x * blockDim.x + threadIdx.x;
        int c = seg[p];
        float invn = __frcp_rn(fmaxf(g_counts[c], 1.0f));
        const float4* s4 = (const float4*)&g_sums[c * ED];
        float4 s0 = s4[0], s1 = s4[1], s2 = s4[2], s3 = s4[3];
        float v[ED];
#pragma unroll
        for (int e = 0; e < ED; e++) v[e] = emb[(size_t)e * PIX + p];
        float dot = s0.x * v[0]  + s0.y * v[1]  + s0.z * v[2]  + s0.w * v[3]
                  + s1.x * v[4]  + s1.y * v[5]  + s1.z * v[6]  + s1.w * v[7]
                  + s2.x * v[8]  + s2.y * v[9]  + s2.z * v[10] + s2.w * v[11]
                  + s3.x * v[12] + s3.y * v[13] + s3.z * v[14] + s3.w * v[15];
        // (1 - dot*invn) - DELTA_VAR = 0.5 - dot*invn, then per-pixel / n
        float t = fmaxf(0.5f - dot * invn, 0.0f) * invn;
        t = block_reduce(t);
        if (threadIdx.x == 0) atomicAdd(&g_acc[1], t);
    } else {
        // ---- inter term ----
        int i = (blockIdx.x - NBLK_INTRA) * blockDim.x + threadIdx.x;
        int u = edges[i];
        int v = edges[NEDGE + i];
        float invu = __frcp_rn(fmaxf(g_counts[u], 1.0f));
        float invv = __frcp_rn(fmaxf(g_counts[v], 1.0f));
        const float4* su = (const float4*)&g_sums[u * ED];
        const float4* sv = (const float4*)&g_sums[v * ED];
        float dot = 0.0f;
#pragma unroll
        for (int j = 0; j < 4; j++) {
            float4 a = su[j], b = sv[j];
            dot += a.x * b.x + a.y * b.y + a.z * b.z + a.w * b.w;
        }
        float d_inter = 1.0f - dot * invu * invv;
        float t = fmaxf(DELTA_DIST - d_inter * w[i], 0.0f);
        t = block_reduce(t);
        if (threadIdx.x == 0) atomicAdd(&g_acc[0], t);
    }
}

// k_final: ALPHA * inter/NE + BETA * intra/C
__global__ void k_final(float* __restrict__ out) {
    out[0] = g_acc[0] / (float)NEDGE + g_acc[1] / (float)CSEG;
}

// ---------------------------------------------------------------------------
extern "C" void kernel_launch(void* const* d_in, const int* in_sizes, int n_in,
                              void* d_out, int out_size) {
    const float* emb   = (const float*)d_in[0];   // (1,16,1024,1024) f32
    const float* w     = (const float*)d_in[1];   // (NE,) f32
    const int*   seg   = (const int*)  d_in[2];   // (1,1,1024,1024) i32
    const int*   edges = (const int*)  d_in[3];   // (2,NE) i32
    float*       out   = (float*)d_out;

    kz_zero <<<(CSEG * ED + 255) / 256, 256>>>();
    k_segsum<<<PIX / 256, 256>>>(emb, seg);
    k_fused <<<NBLK_INTRA + NBLK_INTER, 256>>>(emb, seg, edges, w);
    k_final <<<1, 1>>>(out);
}

// round 13
// speedup vs baseline: 1.4916x; 1.0621x over previous
#include <cuda_runtime.h>
#include <cuda_bf16.h>

// Problem constants (fixed by the reference)
#define CSEG 4096
#define ED   16
#define PIX  (1024*1024)
#define NEDGE 16384
#define DELTA_VAR  0.5f
#define DELTA_DIST 1.5f

#define GRID_F 148
#define TBLK   1024
// dynamic smem: 4096 rows x 8 uint32 (bf16x2 means) + 4096 f32 invn
#define SMEM_MEAN_BYTES (CSEG * 8 * 4)      // 131072
#define SMEM_DYN        (SMEM_MEAN_BYTES + CSEG * 4)  // 147456

// Scratch (device globals — no runtime allocation allowed)
__device__ __align__(128) float g_sums[CSEG * ED];   // 256 KB segment sums
__device__ float g_counts[CSEG];
__device__ float g_acc[2];   // [0]=inter sum, [1]=intra sum
__device__ unsigned int g_done;

// ---------------------------------------------------------------------------
// Vector reduction to global memory (sm_90+): one instruction for 4 floats.
__device__ __forceinline__ void red_add_v4(float* addr, float a, float b, float c, float d) {
    asm volatile("red.global.add.v4.f32 [%0], {%1, %2, %3, %4};"
                 :: "l"(addr), "f"(a), "f"(b), "f"(c), "f"(d) : "memory");
}

__device__ __forceinline__ float warp_reduce(float v) {
    v += __shfl_down_sync(0xFFFFFFFFu, v, 16);
    v += __shfl_down_sync(0xFFFFFFFFu, v, 8);
    v += __shfl_down_sync(0xFFFFFFFFu, v, 4);
    v += __shfl_down_sync(0xFFFFFFFFu, v, 2);
    v += __shfl_down_sync(0xFFFFFFFFu, v, 1);
    return v;
}

// Block reduction for up to 1024 threads: full sum valid on thread 0.
__device__ __forceinline__ float block_reduce(float v, float* s) {
    int lane = threadIdx.x & 31;
    int wid  = threadIdx.x >> 5;
    v = warp_reduce(v);
    if (lane == 0) s[wid] = v;
    __syncthreads();
    if (wid == 0) {
        int nw = blockDim.x >> 5;
        v = (lane < nw) ? s[lane] : 0.0f;
        v = warp_reduce(v);
    }
    return v;
}

// ---------------------------------------------------------------------------
// kz: zero accumulators (graph replays re-run every launch)
__global__ void kz_zero() {
    int i = blockIdx.x * blockDim.x + threadIdx.x;
    if (i < CSEG * ED) g_sums[i] = 0.0f;
    if (i < CSEG)      g_counts[i] = 0.0f;
    if (i < 2)         g_acc[i] = 0.0f;
}

// k_segsum: segment sums + counts. One thread per pixel; 16 coalesced strided
// channel loads, 4 vector reds + 1 scalar red. Bound by LTS atomic-word rate.
__global__ void __launch_bounds__(256) k_segsum(const float* __restrict__ emb,
                                                const int*   __restrict__ seg) {
    int p = blockIdx.x * blockDim.x + threadIdx.x;
    int c = seg[p];
    float v[ED];
#pragma unroll
    for (int e = 0; e < ED; e++) v[e] = emb[(size_t)e * PIX + p];
    float* base = &g_sums[c * ED];
    red_add_v4(base +  0, v[0],  v[1],  v[2],  v[3]);
    red_add_v4(base +  4, v[4],  v[5],  v[6],  v[7]);
    red_add_v4(base +  8, v[8],  v[9],  v[10], v[11]);
    red_add_v4(base + 12, v[12], v[13], v[14], v[15]);
    atomicAdd(&g_counts[c], 1.0f);
}

// k_fused: smem-resident bf16 mean table (144 KB), then
//   - intra hinge over all pixels (grid-stride, random gather hits SMEM)
//   - inter hinge over RAG edges (first 16 blocks)
//   - last-block-done finalize writes the output scalar.
__global__ void __launch_bounds__(TBLK, 1) k_fused(const float* __restrict__ emb,
                                                   const int*   __restrict__ seg,
                                                   const int*   __restrict__ edges,
                                                   const float* __restrict__ w,
                                                   float* __restrict__ out) {
    extern __shared__ char dyn[];
    unsigned int* s_mean = (unsigned int*)dyn;                    // [CSEG*8] bf16x2
    float*        s_invn = (float*)(dyn + SMEM_MEAN_BYTES);       // [CSEG]
    __shared__ float sred[32];

    // ---- build the table: means (bf16x2 packed) + invn ----
    for (int s = threadIdx.x; s < CSEG; s += TBLK) {
        const float4* src = (const float4*)&g_sums[s * ED];
        float4 a = src[0], b = src[1], c4 = src[2], d = src[3];
        float inv = __frcp_rn(fmaxf(g_counts[s], 1.0f));
        float m[ED] = { a.x*inv,  a.y*inv,  a.z*inv,  a.w*inv,
                        b.x*inv,  b.y*inv,  b.z*inv,  b.w*inv,
                        c4.x*inv, c4.y*inv, c4.z*inv, c4.w*inv,
                        d.x*inv,  d.y*inv,  d.z*inv,  d.w*inv };
        unsigned int* row = &s_mean[s * 8];
#pragma unroll
        for (int j = 0; j < 8; j++) {
            __nv_bfloat162 h = __floats2bfloat162_rn(m[2*j], m[2*j + 1]);
            row[j] = *(unsigned int*)&h;
        }
        s_invn[s] = inv;
    }
    __syncthreads();

    // ---- intra term: grid-stride over pixels ----
    float h_intra = 0.0f;
    for (int p = blockIdx.x * TBLK + threadIdx.x; p < PIX; p += GRID_F * TBLK) {
        int c = seg[p];
        float v[ED];
#pragma unroll
        for (int e = 0; e < ED; e++) v[e] = emb[(size_t)e * PIX + p];
        const uint4* row = (const uint4*)&s_mean[c * 8];
        uint4 r0 = row[0], r1 = row[1];
        unsigned int u[8] = { r0.x, r0.y, r0.z, r0.w, r1.x, r1.y, r1.z, r1.w };
        float dot = 0.0f;
#pragma unroll
        for (int j = 0; j < 8; j++) {
            float lo = __uint_as_float(u[j] << 16);
            float hi = __uint_as_float(u[j] & 0xFFFF0000u);
            dot += lo * v[2*j] + hi * v[2*j + 1];
        }
        // (1 - dot) - DELTA_VAR = 0.5 - dot, then per-pixel / n
        h_intra += fmaxf(0.5f - dot, 0.0f) * s_invn[c];
    }

    // ---- inter term: first 16 blocks cover 16384 edges ----
    float h_inter = 0.0f;
    int ei = blockIdx.x * TBLK + threadIdx.x;
    if (ei < NEDGE) {
        int eu = edges[ei];
        int ev = edges[NEDGE + ei];
        const uint4* ru4 = (const uint4*)&s_mean[eu * 8];
        const uint4* rv4 = (const uint4*)&s_mean[ev * 8];
        uint4 a0 = ru4[0], a1 = ru4[1], b0 = rv4[0], b1 = rv4[1];
        unsigned int ua[8] = { a0.x, a0.y, a0.z, a0.w, a1.x, a1.y, a1.z, a1.w };
        unsigned int ub[8] = { b0.x, b0.y, b0.z, b0.w, b1.x, b1.y, b1.z, b1.w };
        float dm = 0.0f;
#pragma unroll
        for (int j = 0; j < 8; j++) {
            float alo = __uint_as_float(ua[j] << 16);
            float ahi = __uint_as_float(ua[j] & 0xFFFF0000u);
            float blo = __uint_as_float(ub[j] << 16);
            float bhi = __uint_as_float(ub[j] & 0xFFFF0000u);
            dm += alo * blo + ahi * bhi;
        }
        float d_inter = 1.0f - dm;
        h_inter = fmaxf(DELTA_DIST - d_inter * w[ei], 0.0f);
    }

    // ---- reductions + finalize ----
    float t1 = block_reduce(h_intra, sred);
    if (threadIdx.x == 0) atomicAdd(&g_acc[1], t1);
    __syncthreads();
    float t0 = block_reduce(h_inter, sred);
    if (threadIdx.x == 0) atomicAdd(&g_acc[0], t0);

    if (threadIdx.x == 0) {
        __threadfence();
        unsigned int v = atomicAdd(&g_done, 1u);
        if (v == GRID_F - 1) {
            float inter = atomicAdd(&g_acc[0], 0.0f);
            float intra = atomicAdd(&g_acc[1], 0.0f);
            out[0] = inter / (float)NEDGE + intra / (float)CSEG;
            g_done = 0;           // reset for next graph replay
            __threadfence();
        }
    }
}

// ---------------------------------------------------------------------------
extern "C" void kernel_launch(void* const* d_in, const int* in_sizes, int n_in,
                              void* d_out, int out_size) {
    const float* emb   = (const float*)d_in[0];   // (1,16,1024,1024) f32
    const float* w     = (const float*)d_in[1];   // (NE,) f32
    const int*   seg   = (const int*)  d_in[2];   // (1,1,1024,1024) i32
    const int*   edges = (const int*)  d_in[3];   // (2,NE) i32
    float*       out   = (float*)d_out;

    cudaFuncSetAttribute(k_fused, cudaFuncAttributeMaxDynamicSharedMemorySize, SMEM_DYN);

    kz_zero <<<(CSEG * ED + 255) / 256, 256>>>();
    k_segsum<<<PIX / 256, 256>>>(emb, seg);
    k_fused <<<GRID_F, TBLK, SMEM_DYN>>>(emb, seg, edges, w, out);
}